// round 12
// baseline (speedup 1.0000x reference)
#include <cuda_runtime.h>
#include <cuda_bf16.h>
#include <math.h>
#include <stdint.h>

#define E_DIM 256
#define N_MAX 8192
#define TILE_M 128
#define TILE_N 64
#define CHUNK 64
#define NCHUNK (E_DIM / CHUNK)        // 4
#define SAW 72                         // smem row stride in bf16 (144B)
#define STAGE_A (TILE_M * SAW * 2)     // 18432
#define STAGE_B (TILE_N * SAW * 2)     // 9216
#define GRID_RELU 444                  // 148 SMs * 3 CTAs

// ---------------- device scratch ----------------
__device__ __nv_bfloat16 g_xb[N_MAX * E_DIM];
__device__ int      g_target[N_MAX];
__device__ int      g_rowsL[N_MAX];
__device__ int      g_rowsN[N_MAX];
__device__ float    g_S[4][E_DIM];
__device__ int      g_cntL, g_cntN;
__device__ double   g_base;
__device__ double   g_sum;
__device__ unsigned g_done;

// ---------------- helpers ----------------
__device__ __forceinline__ uint32_t smem_u32(const void* p) {
    uint32_t a;
    asm("{ .reg .u64 t; cvta.to.shared.u64 t, %1; cvt.u32.u64 %0, t; }" : "=r"(a) : "l"(p));
    return a;
}
__device__ __forceinline__ void cp_async16z(uint32_t dst, const void* src, int sz) {
    asm volatile("cp.async.cg.shared.global [%0], [%1], 16, %2;"
                 :: "r"(dst), "l"(src), "r"(sz) : "memory");
}
__device__ __forceinline__ void cp_commit() {
    asm volatile("cp.async.commit_group;" ::: "memory");
}
__device__ __forceinline__ void cp_wait1() {
    asm volatile("cp.async.wait_group 1;" ::: "memory");
}
__device__ __forceinline__ void cp_wait0() {
    asm volatile("cp.async.wait_group 0;" ::: "memory");
}
__device__ __forceinline__ void ldsm_x4(uint32_t* r, uint32_t addr) {
    asm volatile("ldmatrix.sync.aligned.m8n8.x4.shared.b16 {%0,%1,%2,%3}, [%4];"
                 : "=r"(r[0]), "=r"(r[1]), "=r"(r[2]), "=r"(r[3]) : "r"(addr));
}
__device__ __forceinline__ void mma_16816(float* d, const uint32_t* a, const uint32_t* b) {
    asm volatile(
        "mma.sync.aligned.m16n8k16.row.col.f32.bf16.bf16.f32 "
        "{%0,%1,%2,%3}, {%4,%5,%6,%7}, {%8,%9}, {%0,%1,%2,%3};"
        : "+f"(d[0]), "+f"(d[1]), "+f"(d[2]), "+f"(d[3])
        : "r"(a[0]), "r"(a[1]), "r"(a[2]), "r"(a[3]), "r"(b[0]), "r"(b[1]));
}

// ---------------- K1: normalize (warp per row) + block 0 target decode ----------------
__global__ void prep_kernel(const float* __restrict__ x, const int* __restrict__ traw, int n) {
    const int tid = threadIdx.x;
    const int row = blockIdx.x * 8 + (tid >> 5);
    const int lane = tid & 31;

    const float4* src = (const float4*)(x + (size_t)row * E_DIM + lane * 8);
    float4 v0 = src[0];
    float4 v1 = src[1];
    float s = v0.x * v0.x + v0.y * v0.y + v0.z * v0.z + v0.w * v0.w
            + v1.x * v1.x + v1.y * v1.y + v1.z * v1.z + v1.w * v1.w;
    #pragma unroll
    for (int o = 16; o > 0; o >>= 1) s += __shfl_xor_sync(0xffffffffu, s, o);
    const float inv = 1.0f / fmaxf(sqrtf(s), 1e-8f);

    uint32_t p[4];
    p[0] = (uint32_t)__bfloat16_as_ushort(__float2bfloat16(v0.x * inv))
         | ((uint32_t)__bfloat16_as_ushort(__float2bfloat16(v0.y * inv)) << 16);
    p[1] = (uint32_t)__bfloat16_as_ushort(__float2bfloat16(v0.z * inv))
         | ((uint32_t)__bfloat16_as_ushort(__float2bfloat16(v0.w * inv)) << 16);
    p[2] = (uint32_t)__bfloat16_as_ushort(__float2bfloat16(v1.x * inv))
         | ((uint32_t)__bfloat16_as_ushort(__float2bfloat16(v1.y * inv)) << 16);
    p[3] = (uint32_t)__bfloat16_as_ushort(__float2bfloat16(v1.z * inv))
         | ((uint32_t)__bfloat16_as_ushort(__float2bfloat16(v1.w * inv)) << 16);
    *(uint4*)(g_xb + (size_t)row * E_DIM + lane * 8) = make_uint4(p[0], p[1], p[2], p[3]);

    if (blockIdx.x == 0) {
        __shared__ int s_flag;
        if (tid == 0) { s_flag = 0; g_sum = 0.0; g_done = 0u; }
        for (int i = tid; i < 4 * E_DIM; i += blockDim.x) ((float*)g_S)[i] = 0.f;
        __syncthreads();
        int f = 0;
        for (int i = 2 * tid + 1; i < n; i += 2 * blockDim.x)
            if (traw[i] != 0) f = 1;
        if (f) atomicOr(&s_flag, 1);
        __syncthreads();
        const int is64 = (s_flag == 0);
        for (int i = tid; i < n; i += blockDim.x)
            g_target[i] = is64 ? traw[2 * i] : traw[i];
    }
}

// ---------------- K2: per-class sums (64 rows per block) ----------------
__global__ void classsum_kernel(int n) {
    const int t = threadIdx.x;
    const int r0 = blockIdx.x * 64;
    float a0 = 0.f, a1 = 0.f, a2 = 0.f, a3 = 0.f;
    #pragma unroll 4
    for (int r = 0; r < 64; r++) {
        const int row = r0 + r;
        const float v = __bfloat162float(g_xb[row * E_DIM + t]);
        const int c = g_target[row];
        if (c == 0) a0 += v; else if (c == 1) a1 += v; else if (c == 2) a2 += v; else a3 += v;
    }
    atomicAdd(&g_S[0][t], a0);
    atomicAdd(&g_S[1][t], a1);
    atomicAdd(&g_S[2][t], a2);
    atomicAdd(&g_S[3][t], a3);
}

// ---------------- K3: closed-form same-class loss + gather lists ----------------
__global__ void scalar_kernel(int n) {
    const int t = threadIdx.x;
    __shared__ int cnt[4];
    __shared__ int sL, sN, Lsh;
    __shared__ float sacc[8];
    if (t < 4) cnt[t] = 0;
    if (t < 8) sacc[t] = 0.f;
    if (t == 0) { sL = 0; sN = 0; }
    __syncthreads();

    for (int i = t; i < n; i += blockDim.x) atomicAdd(&cnt[g_target[i] & 3], 1);
    __syncthreads();
    if (t == 0) Lsh = (cnt[3] > 0) ? 3 : (cnt[2] > 0) ? 2 : (cnt[1] > 0) ? 1 : 0;
    __syncthreads();
    const int L = Lsh;

    for (int i = t; i < n; i += blockDim.x) {
        if (g_target[i] == L) g_rowsL[atomicAdd(&sL, 1)] = i;
        else                  g_rowsN[atomicAdd(&sN, 1)] = i;
    }

    const float s0 = g_S[0][t], s1 = g_S[1][t], s2 = g_S[2][t], s3 = g_S[3][t];
    const float sAll = s0 + s1 + s2 + s3;
    const float si[4] = {s0, s1, s2, s3};
    #pragma unroll
    for (int i = 0; i < 4; i++) {
        atomicAdd(&sacc[i], si[i] * si[i]);
        const float cd = sAll - si[i];
        atomicAdd(&sacc[4 + i], cd * cd);
    }
    __syncthreads();

    if (t == 0) {
        double base = 0.0;
        for (int i = 0; i < 4; i++) {
            const double m = (double)cnt[i];
            if (cnt[i] > 0) {
                const double M = (double)n - m;
                const double pairs = m * (m - 1.0) * 0.5 + M * (M - 1.0) * 0.5;
                const double sumcos = ((double)sacc[i] - m) * 0.5 + ((double)sacc[4 + i] - M) * 0.5;
                base += (pairs - sumcos) / m;
            }
        }
        g_base = base;
        g_cntL = sL;
        g_cntN = sN;
    }
}

// ---------------- K4: persistent relu-margin GEMM (indirect loads), fused finalize ----------------
#define OFF_RED  0
#define OFF_ROWS 64     // 192 ints: [0:128) A-tile row ids, [128:192) B-tile row ids (-1 = pad)
#define OFF_A    1024
#define OFF_B    (OFF_A + 2 * STAGE_A)
#define SMEM_TOTAL (OFF_B + 2 * STAGE_B)

__global__ __launch_bounds__(256, 3) void relu_kernel(float* __restrict__ out, double invN) {
    extern __shared__ char smem[];
    const uint32_t sbase = smem_u32(smem);
    int* sRows = (int*)(smem + OFF_ROWS);
    const int tid = threadIdx.x;
    const int wid = tid >> 5;
    const int lid = tid & 31;

    const int cntL = g_cntL, cntN = g_cntN;
    const int nbi = (cntL + TILE_M - 1) / TILE_M;
    const int nbj = (cntN + TILE_N - 1) / TILE_N;
    const int nTilesTot = nbi * nbj;

    // warp decomposition: 4 row-groups x 2 col-groups of 32x32
    const int rbase = (wid & 3) * 32;
    const int cbase = (wid >> 2) * 32;
    const int mi = lid >> 3;
    const int mr = lid & 7;
    const uint32_t aOff = (uint32_t)((rbase + mr + (mi & 1) * 8) * SAW + (mi >> 1) * 8) * 2u;
    const uint32_t bOff = (uint32_t)((cbase + mr + (mi >> 1) * 8) * SAW + (mi & 1) * 8) * 2u;

    float local = 0.f;

    for (int t = blockIdx.x; t < nTilesTot; t += gridDim.x) {
        const int bi = t / nbj;
        const int bj = t - bi * nbj;

        __syncthreads();   // previous tile fully done (all cp groups drained by wait0)
        if (tid < TILE_M) {
            const int gi = bi * TILE_M + tid;
            sRows[tid] = (gi < cntL) ? g_rowsL[gi] : -1;
        } else if (tid < TILE_M + TILE_N) {
            const int gj = bj * TILE_N + (tid - TILE_M);
            sRows[tid] = (gj < cntN) ? g_rowsN[gj] : -1;
        }
        __syncthreads();

        auto load_chunk = [&](int c) {
            if (c < NCHUNK) {
                const int stage = c & 1;
                const uint32_t dA = sbase + OFF_A + stage * STAGE_A;
                const uint32_t dB = sbase + OFF_B + stage * STAGE_B;
                #pragma unroll
                for (int it = 0; it < 4; it++) {     // A: 1024 vecs
                    const int v = tid + it * 256;
                    const int row = v >> 3;
                    const int q = v & 7;
                    const int idx = sRows[row];
                    const uint32_t d = (uint32_t)(row * SAW + q * 8) * 2u;
                    const void* src = g_xb + (size_t)max(idx, 0) * E_DIM + c * CHUNK + q * 8;
                    cp_async16z(dA + d, src, (idx >= 0) ? 16 : 0);
                }
                #pragma unroll
                for (int it = 0; it < 2; it++) {     // B: 512 vecs
                    const int v = tid + it * 256;
                    const int row = v >> 3;
                    const int q = v & 7;
                    const int idx = sRows[TILE_M + row];
                    const uint32_t d = (uint32_t)(row * SAW + q * 8) * 2u;
                    const void* src = g_xb + (size_t)max(idx, 0) * E_DIM + c * CHUNK + q * 8;
                    cp_async16z(dB + d, src, (idx >= 0) ? 16 : 0);
                }
            }
            cp_commit();
        };

        load_chunk(0);

        float acc[2][4][4];
        #pragma unroll
        for (int mt = 0; mt < 2; mt++)
            #pragma unroll
            for (int nt = 0; nt < 4; nt++)
                #pragma unroll
                for (int q = 0; q < 4; q++) acc[mt][nt][q] = 0.f;

        #pragma unroll
        for (int c = 0; c < NCHUNK; c++) {
            const int stage = c & 1;
            if (c + 1 < NCHUNK) { load_chunk(c + 1); cp_wait1(); }
            else                { cp_commit(); cp_wait0(); }
            __syncthreads();

            const uint32_t aBase = sbase + OFF_A + stage * STAGE_A + aOff;
            const uint32_t bBase = sbase + OFF_B + stage * STAGE_B + bOff;

            #pragma unroll
            for (int k = 0; k < CHUNK; k += 16) {
                uint32_t af[2][4];
                uint32_t bf[4][2];
                #pragma unroll
                for (int mt = 0; mt < 2; mt++)
                    ldsm_x4(af[mt], aBase + (uint32_t)(mt * 16 * SAW + k) * 2u);
                #pragma unroll
                for (int bt = 0; bt < 2; bt++) {
                    uint32_t r[4];
                    ldsm_x4(r, bBase + (uint32_t)(bt * 16 * SAW + k) * 2u);
                    bf[2 * bt][0] = r[0]; bf[2 * bt][1] = r[1];
                    bf[2 * bt + 1][0] = r[2]; bf[2 * bt + 1][1] = r[3];
                }
                #pragma unroll
                for (int mt = 0; mt < 2; mt++)
                    #pragma unroll
                    for (int nt = 0; nt < 4; nt++)
                        mma_16816(acc[mt][nt], af[mt], bf[nt]);
            }
            __syncthreads();   // all warps done with this stage before it is refilled
        }

        // relu(cos - 0.5); zero-filled pad rows give relu(-0.5) = 0
        #pragma unroll
        for (int mt = 0; mt < 2; mt++)
            #pragma unroll
            for (int nt = 0; nt < 4; nt++)
                #pragma unroll
                for (int q = 0; q < 4; q++)
                    local += fmaxf(acc[mt][nt][q] - 0.5f, 0.0f);
    }

    // block reduce + fused finalize (all GRID_RELU blocks participate)
    #pragma unroll
    for (int o = 16; o > 0; o >>= 1) local += __shfl_xor_sync(0xffffffffu, local, o);
    float* red = (float*)(smem + OFF_RED);
    __syncthreads();
    if (lid == 0) red[wid] = local;
    __syncthreads();
    if (tid == 0) {
        float z = 0.f;
        #pragma unroll
        for (int i = 0; i < 8; i++) z += red[i];
        atomicAdd(&g_sum, (double)z);
        __threadfence();
        const unsigned done = atomicAdd(&g_done, 1u);
        if (done == (unsigned)gridDim.x - 1u) {
            double total = *(volatile double*)&g_sum;
            out[0] = (float)((g_base + total) * invN);
        }
    }
}

extern "C" void kernel_launch(void* const* d_in, const int* in_sizes, int n_in,
                              void* d_out, int out_size) {
    const float* x = (const float*)d_in[0];
    const int* traw = (const int*)d_in[1];
    float* out = (float*)d_out;

    const int n = in_sizes[1];          // 8192
    const double invN = 1.0 / (double)n;

    cudaFuncSetAttribute(relu_kernel, cudaFuncAttributeMaxDynamicSharedMemorySize, SMEM_TOTAL);

    prep_kernel<<<n / 8, 256>>>(x, traw, n);
    classsum_kernel<<<n / 64, 256>>>(n);
    scalar_kernel<<<1, 256>>>(n);
    relu_kernel<<<GRID_RELU, 256, SMEM_TOTAL>>>(out, invN);
}

// round 13
// speedup vs baseline: 1.0855x; 1.0855x over previous
#include <cuda_runtime.h>
#include <cuda_bf16.h>
#include <math.h>
#include <stdint.h>

#define E_DIM 256
#define N_MAX 8192
#define TILE_M 128
#define TILE_N 64
#define CHUNK 64
#define NCHUNK (E_DIM / CHUNK)        // 4
#define SAW 72                         // smem row stride in bf16 (144B)
#define STAGE_A (TILE_M * SAW * 2)     // 18432
#define STAGE_B (TILE_N * SAW * 2)     // 9216
#define GRID_RELU 444                  // 148 SMs * 3 CTAs
#define CS_BLOCKS 64                   // classsum blocks (128 rows each)

// ---------------- device scratch ----------------
__device__ __nv_bfloat16 g_xb[N_MAX * E_DIM];
__device__ int      g_target[N_MAX];
__device__ int      g_rowsL[N_MAX];
__device__ int      g_rowsN[N_MAX];
__device__ float    g_Spart[CS_BLOCKS][4][E_DIM];   // per-block partial class sums
__device__ int      g_cntL, g_cntN;
__device__ double   g_base;
__device__ double   g_sum;
__device__ unsigned g_done;
__device__ unsigned g_csdone;

// ---------------- helpers ----------------
__device__ __forceinline__ uint32_t smem_u32(const void* p) {
    uint32_t a;
    asm("{ .reg .u64 t; cvta.to.shared.u64 t, %1; cvt.u32.u64 %0, t; }" : "=r"(a) : "l"(p));
    return a;
}
__device__ __forceinline__ void cp_async16z(uint32_t dst, const void* src, int sz) {
    asm volatile("cp.async.cg.shared.global [%0], [%1], 16, %2;"
                 :: "r"(dst), "l"(src), "r"(sz) : "memory");
}
__device__ __forceinline__ void cp_commit() {
    asm volatile("cp.async.commit_group;" ::: "memory");
}
__device__ __forceinline__ void cp_wait1() {
    asm volatile("cp.async.wait_group 1;" ::: "memory");
}
__device__ __forceinline__ void cp_wait0() {
    asm volatile("cp.async.wait_group 0;" ::: "memory");
}
__device__ __forceinline__ void ldsm_x4(uint32_t* r, uint32_t addr) {
    asm volatile("ldmatrix.sync.aligned.m8n8.x4.shared.b16 {%0,%1,%2,%3}, [%4];"
                 : "=r"(r[0]), "=r"(r[1]), "=r"(r[2]), "=r"(r[3]) : "r"(addr));
}
__device__ __forceinline__ void mma_16816(float* d, const uint32_t* a, const uint32_t* b) {
    asm volatile(
        "mma.sync.aligned.m16n8k16.row.col.f32.bf16.bf16.f32 "
        "{%0,%1,%2,%3}, {%4,%5,%6,%7}, {%8,%9}, {%0,%1,%2,%3};"
        : "+f"(d[0]), "+f"(d[1]), "+f"(d[2]), "+f"(d[3])
        : "r"(a[0]), "r"(a[1]), "r"(a[2]), "r"(a[3]), "r"(b[0]), "r"(b[1]));
}

// ---------------- K1: normalize (warp per row) + block 0 target decode ----------------
__global__ void prep_kernel(const float* __restrict__ x, const int* __restrict__ traw, int n) {
    const int tid = threadIdx.x;
    const int row = blockIdx.x * 8 + (tid >> 5);
    const int lane = tid & 31;

    const float4* src = (const float4*)(x + (size_t)row * E_DIM + lane * 8);
    float4 v0 = src[0];
    float4 v1 = src[1];
    float s = v0.x * v0.x + v0.y * v0.y + v0.z * v0.z + v0.w * v0.w
            + v1.x * v1.x + v1.y * v1.y + v1.z * v1.z + v1.w * v1.w;
    #pragma unroll
    for (int o = 16; o > 0; o >>= 1) s += __shfl_xor_sync(0xffffffffu, s, o);
    const float inv = 1.0f / fmaxf(sqrtf(s), 1e-8f);

    uint32_t p[4];
    p[0] = (uint32_t)__bfloat16_as_ushort(__float2bfloat16(v0.x * inv))
         | ((uint32_t)__bfloat16_as_ushort(__float2bfloat16(v0.y * inv)) << 16);
    p[1] = (uint32_t)__bfloat16_as_ushort(__float2bfloat16(v0.z * inv))
         | ((uint32_t)__bfloat16_as_ushort(__float2bfloat16(v0.w * inv)) << 16);
    p[2] = (uint32_t)__bfloat16_as_ushort(__float2bfloat16(v1.x * inv))
         | ((uint32_t)__bfloat16_as_ushort(__float2bfloat16(v1.y * inv)) << 16);
    p[3] = (uint32_t)__bfloat16_as_ushort(__float2bfloat16(v1.z * inv))
         | ((uint32_t)__bfloat16_as_ushort(__float2bfloat16(v1.w * inv)) << 16);
    *(uint4*)(g_xb + (size_t)row * E_DIM + lane * 8) = make_uint4(p[0], p[1], p[2], p[3]);

    if (blockIdx.x == 0) {
        __shared__ int s_flag;
        if (tid == 0) { s_flag = 0; g_sum = 0.0; g_done = 0u; g_csdone = 0u; }
        __syncthreads();
        int f = 0;
        for (int i = 2 * tid + 1; i < n; i += 2 * blockDim.x)
            if (traw[i] != 0) f = 1;
        if (f) atomicOr(&s_flag, 1);
        __syncthreads();
        const int is64 = (s_flag == 0);
        for (int i = tid; i < n; i += blockDim.x)
            g_target[i] = is64 ? traw[2 * i] : traw[i];
    }
}

// ---------------- K2: per-class partial sums + (last block) scalar phase ----------------
__global__ void classsum_kernel(int n) {
    const int t = threadIdx.x;          // dim 0..255
    const int lane = t & 31;
    const int warp = t >> 5;
    const int rowsPer = n / CS_BLOCKS;  // 128
    const int r0 = blockIdx.x * rowsPer;

    float a0 = 0.f, a1 = 0.f, a2 = 0.f, a3 = 0.f;
    #pragma unroll 4
    for (int r = 0; r < rowsPer; r++) {
        const int row = r0 + r;
        const float v = __bfloat162float(g_xb[row * E_DIM + t]);
        const int c = g_target[row];
        if (c == 0) a0 += v; else if (c == 1) a1 += v; else if (c == 2) a2 += v; else a3 += v;
    }
    g_Spart[blockIdx.x][0][t] = a0;
    g_Spart[blockIdx.x][1][t] = a1;
    g_Spart[blockIdx.x][2][t] = a2;
    g_Spart[blockIdx.x][3][t] = a3;
    __threadfence();
    __syncthreads();

    __shared__ unsigned s_last;
    if (t == 0) s_last = (atomicAdd(&g_csdone, 1u) == (unsigned)(CS_BLOCKS - 1));
    __syncthreads();
    if (!s_last) return;

    // ======== scalar phase (runs in exactly one block) ========
    __shared__ int cnt[4];
    __shared__ int sL, sN, Lsh;
    __shared__ float sacc[8];   // [0..3]=|S_i|^2, [4..7]=|S_all-S_i|^2
    if (t < 4) cnt[t] = 0;
    if (t < 8) sacc[t] = 0.f;
    if (t == 0) { sL = 0; sN = 0; }
    __syncthreads();

    // reduce partials (L1-bypass loads: other SMs wrote them)
    float s0 = 0.f, s1 = 0.f, s2 = 0.f, s3 = 0.f;
    #pragma unroll 4
    for (int b = 0; b < CS_BLOCKS; b++) {
        s0 += __ldcg(&g_Spart[b][0][t]);
        s1 += __ldcg(&g_Spart[b][1][t]);
        s2 += __ldcg(&g_Spart[b][2][t]);
        s3 += __ldcg(&g_Spart[b][3][t]);
    }

    // counts via ballots (one shared atomic per warp per class)
    {
        int w0 = 0, w1 = 0, w2 = 0, w3 = 0;
        for (int i = t; i < n; i += blockDim.x) {
            const int c = g_target[i];
            const unsigned m0 = __ballot_sync(0xffffffffu, c == 0);
            const unsigned m1 = __ballot_sync(0xffffffffu, c == 1);
            const unsigned m2 = __ballot_sync(0xffffffffu, c == 2);
            const unsigned m3 = __ballot_sync(0xffffffffu, c == 3);
            if (lane == 0) {
                w0 += __popc(m0); w1 += __popc(m1);
                w2 += __popc(m2); w3 += __popc(m3);
            }
        }
        if (lane == 0) {
            atomicAdd(&cnt[0], w0); atomicAdd(&cnt[1], w1);
            atomicAdd(&cnt[2], w2); atomicAdd(&cnt[3], w3);
        }
    }
    __syncthreads();
    if (t == 0) Lsh = (cnt[3] > 0) ? 3 : (cnt[2] > 0) ? 2 : (cnt[1] > 0) ? 1 : 0;
    __syncthreads();
    const int L = Lsh;

    // gather lists, warp-aggregated offsets (order irrelevant for the sum)
    {
        const unsigned lt = (1u << lane) - 1u;
        for (int i = t; i < n; i += blockDim.x) {
            const bool isL = (g_target[i] == L);
            const unsigned mL = __ballot_sync(0xffffffffu, isL);
            int baseL = 0, baseN = 0;
            if (lane == 0) {
                baseL = atomicAdd(&sL, __popc(mL));
                baseN = atomicAdd(&sN, 32 - __popc(mL));
            }
            baseL = __shfl_sync(0xffffffffu, baseL, 0);
            baseN = __shfl_sync(0xffffffffu, baseN, 0);
            if (isL) g_rowsL[baseL + __popc(mL & lt)] = i;
            else     g_rowsN[baseN + __popc(~mL & lt)] = i;
        }
    }

    // |S_i|^2 and |S_all - S_i|^2 via warp reduce + one atomic per warp
    {
        const float sAll = s0 + s1 + s2 + s3;
        float v[8] = { s0 * s0, s1 * s1, s2 * s2, s3 * s3,
                       (sAll - s0) * (sAll - s0), (sAll - s1) * (sAll - s1),
                       (sAll - s2) * (sAll - s2), (sAll - s3) * (sAll - s3) };
        #pragma unroll
        for (int j = 0; j < 8; j++) {
            float z = v[j];
            #pragma unroll
            for (int o = 16; o > 0; o >>= 1) z += __shfl_xor_sync(0xffffffffu, z, o);
            if (lane == 0) atomicAdd(&sacc[j], z);
        }
    }
    __syncthreads();

    if (t == 0) {
        double base = 0.0;
        for (int i = 0; i < 4; i++) {
            const double m = (double)cnt[i];
            if (cnt[i] > 0) {
                const double M = (double)n - m;
                const double pairs = m * (m - 1.0) * 0.5 + M * (M - 1.0) * 0.5;
                const double sumcos = ((double)sacc[i] - m) * 0.5 + ((double)sacc[4 + i] - M) * 0.5;
                base += (pairs - sumcos) / m;
            }
        }
        g_base = base;
        g_cntL = sL;
        g_cntN = sN;
    }
}

// ---------------- K3: persistent relu-margin GEMM (indirect loads), fused finalize ----------------
#define OFF_RED  0
#define OFF_ROWS 64     // 192 ints: [0:128) A-tile row ids, [128:192) B-tile row ids (-1 = pad)
#define OFF_A    1024
#define OFF_B    (OFF_A + 2 * STAGE_A)
#define SMEM_TOTAL (OFF_B + 2 * STAGE_B)

__global__ __launch_bounds__(256, 3) void relu_kernel(float* __restrict__ out, double invN) {
    extern __shared__ char smem[];
    const uint32_t sbase = smem_u32(smem);
    int* sRows = (int*)(smem + OFF_ROWS);
    const int tid = threadIdx.x;
    const int wid = tid >> 5;
    const int lid = tid & 31;

    const int cntL = g_cntL, cntN = g_cntN;
    const int nbi = (cntL + TILE_M - 1) / TILE_M;
    const int nbj = (cntN + TILE_N - 1) / TILE_N;
    const int nTilesTot = nbi * nbj;

    const int rbase = (wid & 3) * 32;
    const int cbase = (wid >> 2) * 32;
    const int mi = lid >> 3;
    const int mr = lid & 7;
    const uint32_t aOff = (uint32_t)((rbase + mr + (mi & 1) * 8) * SAW + (mi >> 1) * 8) * 2u;
    const uint32_t bOff = (uint32_t)((cbase + mr + (mi >> 1) * 8) * SAW + (mi & 1) * 8) * 2u;

    float local = 0.f;

    for (int t = blockIdx.x; t < nTilesTot; t += gridDim.x) {
        const int bi = t / nbj;
        const int bj = t - bi * nbj;

        __syncthreads();
        if (tid < TILE_M) {
            const int gi = bi * TILE_M + tid;
            sRows[tid] = (gi < cntL) ? g_rowsL[gi] : -1;
        } else if (tid < TILE_M + TILE_N) {
            const int gj = bj * TILE_N + (tid - TILE_M);
            sRows[tid] = (gj < cntN) ? g_rowsN[gj] : -1;
        }
        __syncthreads();

        auto load_chunk = [&](int c) {
            if (c < NCHUNK) {
                const int stage = c & 1;
                const uint32_t dA = sbase + OFF_A + stage * STAGE_A;
                const uint32_t dB = sbase + OFF_B + stage * STAGE_B;
                #pragma unroll
                for (int it = 0; it < 4; it++) {
                    const int v = tid + it * 256;
                    const int row = v >> 3;
                    const int q = v & 7;
                    const int idx = sRows[row];
                    const uint32_t d = (uint32_t)(row * SAW + q * 8) * 2u;
                    const void* src = g_xb + (size_t)max(idx, 0) * E_DIM + c * CHUNK + q * 8;
                    cp_async16z(dA + d, src, (idx >= 0) ? 16 : 0);
                }
                #pragma unroll
                for (int it = 0; it < 2; it++) {
                    const int v = tid + it * 256;
                    const int row = v >> 3;
                    const int q = v & 7;
                    const int idx = sRows[TILE_M + row];
                    const uint32_t d = (uint32_t)(row * SAW + q * 8) * 2u;
                    const void* src = g_xb + (size_t)max(idx, 0) * E_DIM + c * CHUNK + q * 8;
                    cp_async16z(dB + d, src, (idx >= 0) ? 16 : 0);
                }
            }
            cp_commit();
        };

        load_chunk(0);

        float acc[2][4][4];
        #pragma unroll
        for (int mt = 0; mt < 2; mt++)
            #pragma unroll
            for (int nt = 0; nt < 4; nt++)
                #pragma unroll
                for (int q = 0; q < 4; q++) acc[mt][nt][q] = 0.f;

        #pragma unroll
        for (int c = 0; c < NCHUNK; c++) {
            const int stage = c & 1;
            if (c + 1 < NCHUNK) { load_chunk(c + 1); cp_wait1(); }
            else                { cp_commit(); cp_wait0(); }
            __syncthreads();

            const uint32_t aBase = sbase + OFF_A + stage * STAGE_A + aOff;
            const uint32_t bBase = sbase + OFF_B + stage * STAGE_B + bOff;

            #pragma unroll
            for (int k = 0; k < CHUNK; k += 16) {
                uint32_t af[2][4];
                uint32_t bf[4][2];
                #pragma unroll
                for (int mt = 0; mt < 2; mt++)
                    ldsm_x4(af[mt], aBase + (uint32_t)(mt * 16 * SAW + k) * 2u);
                #pragma unroll
                for (int bt = 0; bt < 2; bt++) {
                    uint32_t r[4];
                    ldsm_x4(r, bBase + (uint32_t)(bt * 16 * SAW + k) * 2u);
                    bf[2 * bt][0] = r[0]; bf[2 * bt][1] = r[1];
                    bf[2 * bt + 1][0] = r[2]; bf[2 * bt + 1][1] = r[3];
                }
                #pragma unroll
                for (int mt = 0; mt < 2; mt++)
                    #pragma unroll
                    for (int nt = 0; nt < 4; nt++)
                        mma_16816(acc[mt][nt], af[mt], bf[nt]);
            }
            __syncthreads();
        }

        #pragma unroll
        for (int mt = 0; mt < 2; mt++)
            #pragma unroll
            for (int nt = 0; nt < 4; nt++)
                #pragma unroll
                for (int q = 0; q < 4; q++)
                    local += fmaxf(acc[mt][nt][q] - 0.5f, 0.0f);
    }

    #pragma unroll
    for (int o = 16; o > 0; o >>= 1) local += __shfl_xor_sync(0xffffffffu, local, o);
    float* red = (float*)(smem + OFF_RED);
    __syncthreads();
    if (lid == 0) red[wid] = local;
    __syncthreads();
    if (tid == 0) {
        float z = 0.f;
        #pragma unroll
        for (int i = 0; i < 8; i++) z += red[i];
        atomicAdd(&g_sum, (double)z);
        __threadfence();
        const unsigned done = atomicAdd(&g_done, 1u);
        if (done == (unsigned)gridDim.x - 1u) {
            double total = *(volatile double*)&g_sum;
            out[0] = (float)((g_base + total) * invN);
        }
    }
}

extern "C" void kernel_launch(void* const* d_in, const int* in_sizes, int n_in,
                              void* d_out, int out_size) {
    const float* x = (const float*)d_in[0];
    const int* traw = (const int*)d_in[1];
    float* out = (float*)d_out;

    const int n = in_sizes[1];          // 8192
    const double invN = 1.0 / (double)n;

    cudaFuncSetAttribute(relu_kernel, cudaFuncAttributeMaxDynamicSharedMemorySize, SMEM_TOTAL);

    prep_kernel<<<n / 8, 256>>>(x, traw, n);
    classsum_kernel<<<CS_BLOCKS, 256>>>(n);
    relu_kernel<<<GRID_RELU, 256, SMEM_TOTAL>>>(out, invN);
}

// round 15
// speedup vs baseline: 1.5822x; 1.4576x over previous
#include <cuda_runtime.h>
#include <cuda_bf16.h>
#include <math.h>
#include <stdint.h>

#define E_DIM 256
#define N_MAX 8192
#define TILE_M 128
#define TILE_N 64
#define CHUNK 64
#define NCHUNK (E_DIM / CHUNK)        // 4
#define SAW 72                         // smem row stride in bf16 (144B)
#define STAGE_A (TILE_M * SAW * 2)     // 18432
#define STAGE_B (TILE_N * SAW * 2)     // 9216
#define GRID_RELU 444                  // 148 SMs * 3 CTAs
#define CS_BLOCKS 128
#define ROWS_PER_BLOCK 64              // N / CS_BLOCKS

// ---------------- device scratch ----------------
__device__ __nv_bfloat16 g_xb[N_MAX * E_DIM];
__device__ int      g_target[N_MAX];
__device__ int      g_rowsL[N_MAX];
__device__ int      g_rowsN[N_MAX];
__device__ float    g_Spart[CS_BLOCKS][4][E_DIM];
__device__ int      g_cntL, g_cntN;
__device__ double   g_base;
__device__ double   g_sum;       // zero-init at load; reset by relu last block each run
__device__ unsigned g_done;      // ditto
__device__ unsigned g_csdone;    // reset by K1 last block each run

// ---------------- helpers ----------------
__device__ __forceinline__ uint32_t smem_u32(const void* p) {
    uint32_t a;
    asm("{ .reg .u64 t; cvta.to.shared.u64 t, %1; cvt.u32.u64 %0, t; }" : "=r"(a) : "l"(p));
    return a;
}
__device__ __forceinline__ void cp_async16z(uint32_t dst, const void* src, int sz) {
    asm volatile("cp.async.cg.shared.global [%0], [%1], 16, %2;"
                 :: "r"(dst), "l"(src), "r"(sz) : "memory");
}
__device__ __forceinline__ void cp_commit() {
    asm volatile("cp.async.commit_group;" ::: "memory");
}
__device__ __forceinline__ void cp_wait1() {
    asm volatile("cp.async.wait_group 1;" ::: "memory");
}
__device__ __forceinline__ void cp_wait0() {
    asm volatile("cp.async.wait_group 0;" ::: "memory");
}
__device__ __forceinline__ void ldsm_x4(uint32_t* r, uint32_t addr) {
    asm volatile("ldmatrix.sync.aligned.m8n8.x4.shared.b16 {%0,%1,%2,%3}, [%4];"
                 : "=r"(r[0]), "=r"(r[1]), "=r"(r[2]), "=r"(r[3]) : "r"(addr));
}
__device__ __forceinline__ void mma_16816(float* d, const uint32_t* a, const uint32_t* b) {
    asm volatile(
        "mma.sync.aligned.m16n8k16.row.col.f32.bf16.bf16.f32 "
        "{%0,%1,%2,%3}, {%4,%5,%6,%7}, {%8,%9}, {%0,%1,%2,%3};"
        : "+f"(d[0]), "+f"(d[1]), "+f"(d[2]), "+f"(d[3])
        : "r"(a[0]), "r"(a[1]), "r"(a[2]), "r"(a[3]), "r"(b[0]), "r"(b[1]));
}
__device__ __forceinline__ uint32_t packbf(float a, float b) {
    return (uint32_t)__bfloat16_as_ushort(__float2bfloat16(a))
         | ((uint32_t)__bfloat16_as_ushort(__float2bfloat16(b)) << 16);
}

// ---------------- K1: normalize + class sums + (last block) scalar phase ----------------
__global__ __launch_bounds__(256) void fused_prep_kernel(const float* __restrict__ x,
                                                         const int* __restrict__ traw, int n) {
    const int tid = threadIdx.x;
    const int warp = tid >> 5;
    const int lane = tid & 31;
    const int b = blockIdx.x;

    __shared__ int sTarget[ROWS_PER_BLOCK];
    __shared__ float sStage[8][4][E_DIM];   // 32 KB

    // is64 detection (odd-word scan)
    int f = 0;
    for (int i = 2 * tid + 1; i < n; i += 2 * 256)
        if (traw[i] != 0) f = 1;
    const int is64 = (__syncthreads_or(f) == 0);

    // decode this block's targets
    if (tid < ROWS_PER_BLOCK) {
        const int row = b * ROWS_PER_BLOCK + tid;
        const int tv = is64 ? traw[2 * row] : traw[row];
        sTarget[tid] = tv;
        g_target[row] = tv;
    }
    __syncthreads();

    // normalize 8 rows per warp (two groups of 4, MLP 8), class sums from registers
    float acc[4][8];
    #pragma unroll
    for (int c = 0; c < 4; c++)
        #pragma unroll
        for (int j = 0; j < 8; j++) acc[c][j] = 0.f;

    #pragma unroll
    for (int g = 0; g < 2; g++) {
        const int rbase = b * ROWS_PER_BLOCK + warp * 8 + g * 4;
        float4 v[4][2];
        #pragma unroll
        for (int r = 0; r < 4; r++) {
            const float4* src = (const float4*)(x + (size_t)(rbase + r) * E_DIM + lane * 8);
            v[r][0] = src[0];
            v[r][1] = src[1];
        }
        #pragma unroll
        for (int r = 0; r < 4; r++) {
            float s = v[r][0].x * v[r][0].x + v[r][0].y * v[r][0].y
                    + v[r][0].z * v[r][0].z + v[r][0].w * v[r][0].w
                    + v[r][1].x * v[r][1].x + v[r][1].y * v[r][1].y
                    + v[r][1].z * v[r][1].z + v[r][1].w * v[r][1].w;
            #pragma unroll
            for (int o = 16; o > 0; o >>= 1) s += __shfl_xor_sync(0xffffffffu, s, o);
            const float inv = 1.0f / fmaxf(sqrtf(s), 1e-8f);

            float nv[8] = { v[r][0].x * inv, v[r][0].y * inv, v[r][0].z * inv, v[r][0].w * inv,
                            v[r][1].x * inv, v[r][1].y * inv, v[r][1].z * inv, v[r][1].w * inv };
            uint4 pk = make_uint4(packbf(nv[0], nv[1]), packbf(nv[2], nv[3]),
                                  packbf(nv[4], nv[5]), packbf(nv[6], nv[7]));
            *(uint4*)(g_xb + (size_t)(rbase + r) * E_DIM + lane * 8) = pk;

            const int c = sTarget[warp * 8 + g * 4 + r] & 3;   // uniform across warp
            float* a = acc[c];
            #pragma unroll
            for (int j = 0; j < 8; j++) a[j] += nv[j];
        }
    }

    // stage per-warp sums, reduce across warps, write block partial
    #pragma unroll
    for (int c = 0; c < 4; c++)
        #pragma unroll
        for (int j = 0; j < 8; j++)
            sStage[warp][c][lane * 8 + j] = acc[c][j];
    __syncthreads();
    #pragma unroll
    for (int c = 0; c < 4; c++) {
        float z = 0.f;
        #pragma unroll
        for (int w = 0; w < 8; w++) z += sStage[w][c][tid];
        g_Spart[b][c][tid] = z;
    }
    __threadfence();
    __syncthreads();

    __shared__ unsigned s_last;
    if (tid == 0) s_last = (atomicAdd(&g_csdone, 1u) == (unsigned)(CS_BLOCKS - 1));
    __syncthreads();
    if (!s_last) return;

    // ======== scalar phase (exactly one block) ========
    __shared__ int cnt[4];
    __shared__ int sL, sN, Lsh;
    __shared__ float sacc[8];
    if (tid < 4) cnt[tid] = 0;
    if (tid < 8) sacc[tid] = 0.f;
    if (tid == 0) { sL = 0; sN = 0; }
    __syncthreads();

    float s0 = 0.f, s1 = 0.f, s2 = 0.f, s3 = 0.f;
    #pragma unroll 4
    for (int p = 0; p < CS_BLOCKS; p++) {
        s0 += __ldcg(&g_Spart[p][0][tid]);
        s1 += __ldcg(&g_Spart[p][1][tid]);
        s2 += __ldcg(&g_Spart[p][2][tid]);
        s3 += __ldcg(&g_Spart[p][3][tid]);
    }

    {   // counts via ballots
        int w0 = 0, w1 = 0, w2 = 0, w3 = 0;
        for (int i = tid; i < n; i += 256) {
            const int c = __ldcg(&g_target[i]);
            const unsigned m0 = __ballot_sync(0xffffffffu, c == 0);
            const unsigned m1 = __ballot_sync(0xffffffffu, c == 1);
            const unsigned m2 = __ballot_sync(0xffffffffu, c == 2);
            const unsigned m3 = __ballot_sync(0xffffffffu, c == 3);
            if (lane == 0) { w0 += __popc(m0); w1 += __popc(m1); w2 += __popc(m2); w3 += __popc(m3); }
        }
        if (lane == 0) {
            atomicAdd(&cnt[0], w0); atomicAdd(&cnt[1], w1);
            atomicAdd(&cnt[2], w2); atomicAdd(&cnt[3], w3);
        }
    }
    __syncthreads();
    if (tid == 0) Lsh = (cnt[3] > 0) ? 3 : (cnt[2] > 0) ? 2 : (cnt[1] > 0) ? 1 : 0;
    __syncthreads();
    const int L = Lsh;

    {   // gather lists (warp-aggregated)
        const unsigned lt = (1u << lane) - 1u;
        for (int i = tid; i < n; i += 256) {
            const bool isL = (__ldcg(&g_target[i]) == L);
            const unsigned mL = __ballot_sync(0xffffffffu, isL);
            int baseL = 0, baseN = 0;
            if (lane == 0) {
                baseL = atomicAdd(&sL, __popc(mL));
                baseN = atomicAdd(&sN, 32 - __popc(mL));
            }
            baseL = __shfl_sync(0xffffffffu, baseL, 0);
            baseN = __shfl_sync(0xffffffffu, baseN, 0);
            if (isL) g_rowsL[baseL + __popc(mL & lt)] = i;
            else     g_rowsN[baseN + __popc(~mL & lt)] = i;
        }
    }

    {   // |S_i|^2 and |S_all-S_i|^2
        const float sAll = s0 + s1 + s2 + s3;
        float v[8] = { s0 * s0, s1 * s1, s2 * s2, s3 * s3,
                       (sAll - s0) * (sAll - s0), (sAll - s1) * (sAll - s1),
                       (sAll - s2) * (sAll - s2), (sAll - s3) * (sAll - s3) };
        #pragma unroll
        for (int j = 0; j < 8; j++) {
            float z = v[j];
            #pragma unroll
            for (int o = 16; o > 0; o >>= 1) z += __shfl_xor_sync(0xffffffffu, z, o);
            if (lane == 0) atomicAdd(&sacc[j], z);
        }
    }
    __syncthreads();

    if (tid == 0) {
        double base = 0.0;
        for (int i = 0; i < 4; i++) {
            const double m = (double)cnt[i];
            if (cnt[i] > 0) {
                const double M = (double)n - m;
                const double pairs = m * (m - 1.0) * 0.5 + M * (M - 1.0) * 0.5;
                const double sumcos = ((double)sacc[i] - m) * 0.5 + ((double)sacc[4 + i] - M) * 0.5;
                base += (pairs - sumcos) / m;
            }
        }
        g_base = base;
        g_cntL = sL;
        g_cntN = sN;
        g_csdone = 0u;   // reset for next graph replay
    }
}

// ---------------- K2: persistent relu-margin GEMM (indirect loads), fused finalize ----------------
#define OFF_RED  0
#define OFF_ROWS 64
#define OFF_A    1024
#define OFF_B    (OFF_A + 2 * STAGE_A)
#define SMEM_TOTAL (OFF_B + 2 * STAGE_B)

__global__ __launch_bounds__(256, 3) void relu_kernel(float* __restrict__ out, double invN) {
    extern __shared__ char smem[];
    const uint32_t sbase = smem_u32(smem);
    int* sRows = (int*)(smem + OFF_ROWS);
    const int tid = threadIdx.x;
    const int wid = tid >> 5;
    const int lid = tid & 31;

    const int cntL = g_cntL, cntN = g_cntN;
    const int nbi = (cntL + TILE_M - 1) / TILE_M;
    const int nbj = (cntN + TILE_N - 1) / TILE_N;
    const int nTilesTot = nbi * nbj;

    const int rbase = (wid & 3) * 32;
    const int cbase = (wid >> 2) * 32;
    const int mi = lid >> 3;
    const int mr = lid & 7;
    const uint32_t aOff = (uint32_t)((rbase + mr + (mi & 1) * 8) * SAW + (mi >> 1) * 8) * 2u;
    const uint32_t bOff = (uint32_t)((cbase + mr + (mi >> 1) * 8) * SAW + (mi & 1) * 8) * 2u;

    float local = 0.f;

    for (int t = blockIdx.x; t < nTilesTot; t += gridDim.x) {
        const int bi = t / nbj;
        const int bj = t - bi * nbj;

        __syncthreads();
        if (tid < TILE_M) {
            const int gi = bi * TILE_M + tid;
            sRows[tid] = (gi < cntL) ? g_rowsL[gi] : -1;
        } else if (tid < TILE_M + TILE_N) {
            const int gj = bj * TILE_N + (tid - TILE_M);
            sRows[tid] = (gj < cntN) ? g_rowsN[gj] : -1;
        }
        __syncthreads();

        auto load_chunk = [&](int c) {
            if (c < NCHUNK) {
                const int stage = c & 1;
                const uint32_t dA = sbase + OFF_A + stage * STAGE_A;
                const uint32_t dB = sbase + OFF_B + stage * STAGE_B;
                #pragma unroll
                for (int it = 0; it < 4; it++) {
                    const int v = tid + it * 256;
                    const int row = v >> 3;
                    const int q = v & 7;
                    const int idx = sRows[row];
                    const uint32_t d = (uint32_t)(row * SAW + q * 8) * 2u;
                    const void* src = g_xb + (size_t)max(idx, 0) * E_DIM + c * CHUNK + q * 8;
                    cp_async16z(dA + d, src, (idx >= 0) ? 16 : 0);
                }
                #pragma unroll
                for (int it = 0; it < 2; it++) {
                    const int v = tid + it * 256;
                    const int row = v >> 3;
                    const int q = v & 7;
                    const int idx = sRows[TILE_M + row];
                    const uint32_t d = (uint32_t)(row * SAW + q * 8) * 2u;
                    const void* src = g_xb + (size_t)max(idx, 0) * E_DIM + c * CHUNK + q * 8;
                    cp_async16z(dB + d, src, (idx >= 0) ? 16 : 0);
                }
            }
            cp_commit();
        };

        load_chunk(0);

        float acc[2][4][4];
        #pragma unroll
        for (int mt = 0; mt < 2; mt++)
            #pragma unroll
            for (int nt = 0; nt < 4; nt++)
                #pragma unroll
                for (int q = 0; q < 4; q++) acc[mt][nt][q] = 0.f;

        #pragma unroll
        for (int c = 0; c < NCHUNK; c++) {
            const int stage = c & 1;
            if (c + 1 < NCHUNK) { load_chunk(c + 1); cp_wait1(); }
            else                { cp_commit(); cp_wait0(); }
            __syncthreads();

            const uint32_t aBase = sbase + OFF_A + stage * STAGE_A + aOff;
            const uint32_t bBase = sbase + OFF_B + stage * STAGE_B + bOff;

            #pragma unroll
            for (int k = 0; k < CHUNK; k += 16) {
                uint32_t af[2][4];
                uint32_t bf[4][2];
                #pragma unroll
                for (int mt = 0; mt < 2; mt++)
                    ldsm_x4(af[mt], aBase + (uint32_t)(mt * 16 * SAW + k) * 2u);
                #pragma unroll
                for (int bt = 0; bt < 2; bt++) {
                    uint32_t r[4];
                    ldsm_x4(r, bBase + (uint32_t)(bt * 16 * SAW + k) * 2u);
                    bf[2 * bt][0] = r[0]; bf[2 * bt][1] = r[1];
                    bf[2 * bt + 1][0] = r[2]; bf[2 * bt + 1][1] = r[3];
                }
                #pragma unroll
                for (int mt = 0; mt < 2; mt++)
                    #pragma unroll
                    for (int nt = 0; nt < 4; nt++)
                        mma_16816(acc[mt][nt], af[mt], bf[nt]);
            }
            __syncthreads();
        }

        #pragma unroll
        for (int mt = 0; mt < 2; mt++)
            #pragma unroll
            for (int nt = 0; nt < 4; nt++)
                #pragma unroll
                for (int q = 0; q < 4; q++)
                    local += fmaxf(acc[mt][nt][q] - 0.5f, 0.0f);
    }

    #pragma unroll
    for (int o = 16; o > 0; o >>= 1) local += __shfl_xor_sync(0xffffffffu, local, o);
    float* red = (float*)(smem + OFF_RED);
    __syncthreads();
    if (lid == 0) red[wid] = local;
    __syncthreads();
    if (tid == 0) {
        float z = 0.f;
        #pragma unroll
        for (int i = 0; i < 8; i++) z += red[i];
        atomicAdd(&g_sum, (double)z);
        __threadfence();
        const unsigned done = atomicAdd(&g_done, 1u);
        if (done == (unsigned)gridDim.x - 1u) {
            double total = *(volatile double*)&g_sum;
            out[0] = (float)((g_base + total) * invN);
            g_sum = 0.0;     // reset for next graph replay
            g_done = 0u;
        }
    }
}

extern "C" void kernel_launch(void* const* d_in, const int* in_sizes, int n_in,
                              void* d_out, int out_size) {
    const float* x = (const float*)d_in[0];
    const int* traw = (const int*)d_in[1];
    float* out = (float*)d_out;

    const int n = in_sizes[1];          // 8192
    const double invN = 1.0 / (double)n;

    cudaFuncSetAttribute(relu_kernel, cudaFuncAttributeMaxDynamicSharedMemorySize, SMEM_TOTAL);

    fused_prep_kernel<<<CS_BLOCKS, 256>>>(x, traw, n);
    relu_kernel<<<GRID_RELU, 256, SMEM_TOTAL>>>(out, invN);
}

// round 16
// speedup vs baseline: 1.7861x; 1.1289x over previous
#include <cuda_runtime.h>
#include <cuda_bf16.h>
#include <math.h>
#include <stdint.h>

#define E_DIM 256
#define N_MAX 8192
#define TILE_M 128
#define TILE_N 64
#define CHUNK 64
#define NCHUNK (E_DIM / CHUNK)        // 4
#define SAW 72                         // smem row stride in bf16 (144B)
#define STAGE_A (TILE_M * SAW * 2)     // 18432
#define STAGE_B (TILE_N * SAW * 2)     // 9216
#define GRID_RELU 444                  // 148 SMs * 3 CTAs
#define CS_BLOCKS 128
#define ROWS_PER_BLOCK 64              // N / CS_BLOCKS

// ---------------- device scratch ----------------
__device__ __nv_bfloat16 g_xb[N_MAX * E_DIM];
__device__ int      g_rows4[4][N_MAX];          // per-class row lists (parallel scatter)
__device__ int      g_cls[4];                    // per-class counters (atomic; reset by relu)
__device__ int      g_rowsL[N_MAX];
__device__ int      g_rowsN[N_MAX];
__device__ float    g_Spart[CS_BLOCKS][4][E_DIM];
__device__ int      g_cntL, g_cntN;
__device__ double   g_base;
__device__ double   g_sum;       // reset by relu last block each run
__device__ unsigned g_done;      // ditto
__device__ unsigned g_csdone;    // reset by K1 tail each run

// ---------------- helpers ----------------
__device__ __forceinline__ uint32_t smem_u32(const void* p) {
    uint32_t a;
    asm("{ .reg .u64 t; cvta.to.shared.u64 t, %1; cvt.u32.u64 %0, t; }" : "=r"(a) : "l"(p));
    return a;
}
__device__ __forceinline__ void cp_async16z(uint32_t dst, const void* src, int sz) {
    asm volatile("cp.async.cg.shared.global [%0], [%1], 16, %2;"
                 :: "r"(dst), "l"(src), "r"(sz) : "memory");
}
__device__ __forceinline__ void cp_commit() {
    asm volatile("cp.async.commit_group;" ::: "memory");
}
__device__ __forceinline__ void cp_wait1() {
    asm volatile("cp.async.wait_group 1;" ::: "memory");
}
__device__ __forceinline__ void cp_wait0() {
    asm volatile("cp.async.wait_group 0;" ::: "memory");
}
__device__ __forceinline__ void ldsm_x4(uint32_t* r, uint32_t addr) {
    asm volatile("ldmatrix.sync.aligned.m8n8.x4.shared.b16 {%0,%1,%2,%3}, [%4];"
                 : "=r"(r[0]), "=r"(r[1]), "=r"(r[2]), "=r"(r[3]) : "r"(addr));
}
__device__ __forceinline__ void mma_16816(float* d, const uint32_t* a, const uint32_t* b) {
    asm volatile(
        "mma.sync.aligned.m16n8k16.row.col.f32.bf16.bf16.f32 "
        "{%0,%1,%2,%3}, {%4,%5,%6,%7}, {%8,%9}, {%0,%1,%2,%3};"
        : "+f"(d[0]), "+f"(d[1]), "+f"(d[2]), "+f"(d[3])
        : "r"(a[0]), "r"(a[1]), "r"(a[2]), "r"(a[3]), "r"(b[0]), "r"(b[1]));
}
__device__ __forceinline__ uint32_t packbf(float a, float b) {
    return (uint32_t)__bfloat16_as_ushort(__float2bfloat16(a))
         | ((uint32_t)__bfloat16_as_ushort(__float2bfloat16(b)) << 16);
}

// ---------------- K1: normalize + class sums + class scatter + (last block) tail ----------------
__global__ __launch_bounds__(256) void fused_prep_kernel(const float* __restrict__ x,
                                                         const int* __restrict__ traw, int n) {
    const int tid = threadIdx.x;
    const int warp = tid >> 5;
    const int lane = tid & 31;
    const int b = blockIdx.x;

    __shared__ int sTarget[ROWS_PER_BLOCK];
    __shared__ float sStage[8][4][E_DIM];   // 32 KB

    // is64 detection (odd-word scan)
    int f = 0;
    for (int i = 2 * tid + 1; i < n; i += 2 * 256)
        if (traw[i] != 0) f = 1;
    const int is64 = (__syncthreads_or(f) == 0);

    // decode this block's targets
    if (tid < ROWS_PER_BLOCK) {
        const int row = b * ROWS_PER_BLOCK + tid;
        sTarget[tid] = (is64 ? traw[2 * row] : traw[row]) & 3;
    }
    __syncthreads();

    // class scatter into per-class lists (warp-aggregated atomics; warps 2-7 idle here)
    {
        const int myCls = (tid < ROWS_PER_BLOCK) ? sTarget[tid] : -1;
        const int myRow = b * ROWS_PER_BLOCK + tid;
        const unsigned lt = (1u << lane) - 1u;
        #pragma unroll
        for (int cls = 0; cls < 4; cls++) {
            const unsigned m = __ballot_sync(0xffffffffu, myCls == cls);
            if (m) {
                int base;
                if (lane == 0) base = atomicAdd(&g_cls[cls], __popc(m));
                base = __shfl_sync(0xffffffffu, base, 0);
                if (myCls == cls) g_rows4[cls][base + __popc(m & lt)] = myRow;
            }
        }
    }

    // normalize 8 rows per warp (two groups of 4, MLP 8), class sums from registers
    float acc[4][8];
    #pragma unroll
    for (int c = 0; c < 4; c++)
        #pragma unroll
        for (int j = 0; j < 8; j++) acc[c][j] = 0.f;

    #pragma unroll
    for (int g = 0; g < 2; g++) {
        const int rbase = b * ROWS_PER_BLOCK + warp * 8 + g * 4;
        float4 v[4][2];
        #pragma unroll
        for (int r = 0; r < 4; r++) {
            const float4* src = (const float4*)(x + (size_t)(rbase + r) * E_DIM + lane * 8);
            v[r][0] = src[0];
            v[r][1] = src[1];
        }
        #pragma unroll
        for (int r = 0; r < 4; r++) {
            float s = v[r][0].x * v[r][0].x + v[r][0].y * v[r][0].y
                    + v[r][0].z * v[r][0].z + v[r][0].w * v[r][0].w
                    + v[r][1].x * v[r][1].x + v[r][1].y * v[r][1].y
                    + v[r][1].z * v[r][1].z + v[r][1].w * v[r][1].w;
            #pragma unroll
            for (int o = 16; o > 0; o >>= 1) s += __shfl_xor_sync(0xffffffffu, s, o);
            const float inv = 1.0f / fmaxf(sqrtf(s), 1e-8f);

            float nv[8] = { v[r][0].x * inv, v[r][0].y * inv, v[r][0].z * inv, v[r][0].w * inv,
                            v[r][1].x * inv, v[r][1].y * inv, v[r][1].z * inv, v[r][1].w * inv };
            uint4 pk = make_uint4(packbf(nv[0], nv[1]), packbf(nv[2], nv[3]),
                                  packbf(nv[4], nv[5]), packbf(nv[6], nv[7]));
            *(uint4*)(g_xb + (size_t)(rbase + r) * E_DIM + lane * 8) = pk;

            const int c = sTarget[warp * 8 + g * 4 + r];   // uniform across warp
            float* a = acc[c];
            #pragma unroll
            for (int j = 0; j < 8; j++) a[j] += nv[j];
        }
    }

    // stage per-warp sums, reduce across warps, write block partial
    #pragma unroll
    for (int c = 0; c < 4; c++)
        #pragma unroll
        for (int j = 0; j < 8; j++)
            sStage[warp][c][lane * 8 + j] = acc[c][j];
    __syncthreads();
    #pragma unroll
    for (int c = 0; c < 4; c++) {
        float z = 0.f;
        #pragma unroll
        for (int w = 0; w < 8; w++) z += sStage[w][c][tid];
        g_Spart[b][c][tid] = z;
    }
    __threadfence();
    __syncthreads();

    __shared__ unsigned s_last;
    if (tid == 0) s_last = (atomicAdd(&g_csdone, 1u) == (unsigned)(CS_BLOCKS - 1));
    __syncthreads();
    if (!s_last) return;

    // ======== tail (exactly one block, now mostly parallel copies) ========
    int c4[4];
    #pragma unroll
    for (int c = 0; c < 4; c++) c4[c] = __ldcg(&g_cls[c]);
    const int L = (c4[3] > 0) ? 3 : (c4[2] > 0) ? 2 : (c4[1] > 0) ? 1 : 0;
    const int cntL = c4[L];

    // copy L list -> rowsL ; concat other lists -> rowsN (parallel, high MLP)
    for (int i = tid; i < cntL; i += 256) g_rowsL[i] = __ldcg(&g_rows4[L][i]);
    {
        int off = 0;
        #pragma unroll
        for (int c = 0; c < 4; c++) {
            if (c != L) {
                const int cc = c4[c];
                for (int i = tid; i < cc; i += 256) g_rowsN[off + i] = __ldcg(&g_rows4[c][i]);
                off += cc;
            }
        }
    }

    // reduce Spart (unroll 8, independent loads)
    float s0 = 0.f, s1 = 0.f, s2 = 0.f, s3 = 0.f;
    #pragma unroll 8
    for (int p = 0; p < CS_BLOCKS; p++) {
        s0 += __ldcg(&g_Spart[p][0][tid]);
        s1 += __ldcg(&g_Spart[p][1][tid]);
        s2 += __ldcg(&g_Spart[p][2][tid]);
        s3 += __ldcg(&g_Spart[p][3][tid]);
    }

    __shared__ float sacc[8];
    if (tid < 8) sacc[tid] = 0.f;
    __syncthreads();
    {
        const float sAll = s0 + s1 + s2 + s3;
        float v[8] = { s0 * s0, s1 * s1, s2 * s2, s3 * s3,
                       (sAll - s0) * (sAll - s0), (sAll - s1) * (sAll - s1),
                       (sAll - s2) * (sAll - s2), (sAll - s3) * (sAll - s3) };
        #pragma unroll
        for (int j = 0; j < 8; j++) {
            float z = v[j];
            #pragma unroll
            for (int o = 16; o > 0; o >>= 1) z += __shfl_xor_sync(0xffffffffu, z, o);
            if (lane == 0) atomicAdd(&sacc[j], z);
        }
    }
    __syncthreads();

    if (tid == 0) {
        double base = 0.0;
        for (int i = 0; i < 4; i++) {
            const double m = (double)c4[i];
            if (c4[i] > 0) {
                const double M = (double)n - m;
                const double pairs = m * (m - 1.0) * 0.5 + M * (M - 1.0) * 0.5;
                const double sumcos = ((double)sacc[i] - m) * 0.5 + ((double)sacc[4 + i] - M) * 0.5;
                base += (pairs - sumcos) / m;
            }
        }
        g_base = base;
        g_cntL = cntL;
        g_cntN = n - cntL;
        g_csdone = 0u;   // reset for next graph replay
    }
}

// ---------------- K2: persistent relu-margin GEMM (indirect loads), fused finalize ----------------
#define OFF_RED  0
#define OFF_ROWS 64
#define OFF_A    1024
#define OFF_B    (OFF_A + 2 * STAGE_A)
#define SMEM_TOTAL (OFF_B + 2 * STAGE_B)

__global__ __launch_bounds__(256, 3) void relu_kernel(float* __restrict__ out, double invN) {
    extern __shared__ char smem[];
    const uint32_t sbase = smem_u32(smem);
    int* sRows = (int*)(smem + OFF_ROWS);
    const int tid = threadIdx.x;
    const int wid = tid >> 5;
    const int lid = tid & 31;

    const int cntL = g_cntL, cntN = g_cntN;
    const int nbi = (cntL + TILE_M - 1) / TILE_M;
    const int nbj = (cntN + TILE_N - 1) / TILE_N;
    const int nTilesTot = nbi * nbj;

    const int rbase = (wid & 3) * 32;
    const int cbase = (wid >> 2) * 32;
    const int mi = lid >> 3;
    const int mr = lid & 7;
    const uint32_t aOff = (uint32_t)((rbase + mr + (mi & 1) * 8) * SAW + (mi >> 1) * 8) * 2u;
    const uint32_t bOff = (uint32_t)((cbase + mr + (mi >> 1) * 8) * SAW + (mi & 1) * 8) * 2u;

    float local = 0.f;

    for (int t = blockIdx.x; t < nTilesTot; t += gridDim.x) {
        const int bi = t / nbj;
        const int bj = t - bi * nbj;

        __syncthreads();
        if (tid < TILE_M) {
            const int gi = bi * TILE_M + tid;
            sRows[tid] = (gi < cntL) ? g_rowsL[gi] : -1;
        } else if (tid < TILE_M + TILE_N) {
            const int gj = bj * TILE_N + (tid - TILE_M);
            sRows[tid] = (gj < cntN) ? g_rowsN[gj] : -1;
        }
        __syncthreads();

        auto load_chunk = [&](int c) {
            if (c < NCHUNK) {
                const int stage = c & 1;
                const uint32_t dA = sbase + OFF_A + stage * STAGE_A;
                const uint32_t dB = sbase + OFF_B + stage * STAGE_B;
                #pragma unroll
                for (int it = 0; it < 4; it++) {
                    const int v = tid + it * 256;
                    const int row = v >> 3;
                    const int q = v & 7;
                    const int idx = sRows[row];
                    const uint32_t d = (uint32_t)(row * SAW + q * 8) * 2u;
                    const void* src = g_xb + (size_t)max(idx, 0) * E_DIM + c * CHUNK + q * 8;
                    cp_async16z(dA + d, src, (idx >= 0) ? 16 : 0);
                }
                #pragma unroll
                for (int it = 0; it < 2; it++) {
                    const int v = tid + it * 256;
                    const int row = v >> 3;
                    const int q = v & 7;
                    const int idx = sRows[TILE_M + row];
                    const uint32_t d = (uint32_t)(row * SAW + q * 8) * 2u;
                    const void* src = g_xb + (size_t)max(idx, 0) * E_DIM + c * CHUNK + q * 8;
                    cp_async16z(dB + d, src, (idx >= 0) ? 16 : 0);
                }
            }
            cp_commit();
        };

        load_chunk(0);

        float acc[2][4][4];
        #pragma unroll
        for (int mt = 0; mt < 2; mt++)
            #pragma unroll
            for (int nt = 0; nt < 4; nt++)
                #pragma unroll
                for (int q = 0; q < 4; q++) acc[mt][nt][q] = 0.f;

        #pragma unroll
        for (int c = 0; c < NCHUNK; c++) {
            const int stage = c & 1;
            if (c + 1 < NCHUNK) { load_chunk(c + 1); cp_wait1(); }
            else                { cp_commit(); cp_wait0(); }
            __syncthreads();   // data ready AND all warps done reading the stage being refilled next

            const uint32_t aBase = sbase + OFF_A + stage * STAGE_A + aOff;
            const uint32_t bBase = sbase + OFF_B + stage * STAGE_B + bOff;

            #pragma unroll
            for (int k = 0; k < CHUNK; k += 16) {
                uint32_t af[2][4];
                uint32_t bf[4][2];
                #pragma unroll
                for (int mt = 0; mt < 2; mt++)
                    ldsm_x4(af[mt], aBase + (uint32_t)(mt * 16 * SAW + k) * 2u);
                #pragma unroll
                for (int bt = 0; bt < 2; bt++) {
                    uint32_t r[4];
                    ldsm_x4(r, bBase + (uint32_t)(bt * 16 * SAW + k) * 2u);
                    bf[2 * bt][0] = r[0]; bf[2 * bt][1] = r[1];
                    bf[2 * bt + 1][0] = r[2]; bf[2 * bt + 1][1] = r[3];
                }
                #pragma unroll
                for (int mt = 0; mt < 2; mt++)
                    #pragma unroll
                    for (int nt = 0; nt < 4; nt++)
                        mma_16816(acc[mt][nt], af[mt], bf[nt]);
            }
            // NOTE: no end-of-chunk barrier — next iteration's post-wait sync orders
            // all stage reads before that stage is refilled.
        }

        #pragma unroll
        for (int mt = 0; mt < 2; mt++)
            #pragma unroll
            for (int nt = 0; nt < 4; nt++)
                #pragma unroll
                for (int q = 0; q < 4; q++)
                    local += fmaxf(acc[mt][nt][q] - 0.5f, 0.0f);
    }

    #pragma unroll
    for (int o = 16; o > 0; o >>= 1) local += __shfl_xor_sync(0xffffffffu, local, o);
    float* red = (float*)(smem + OFF_RED);
    __syncthreads();
    if (lid == 0) red[wid] = local;
    __syncthreads();
    if (tid == 0) {
        float z = 0.f;
        #pragma unroll
        for (int i = 0; i < 8; i++) z += red[i];
        atomicAdd(&g_sum, (double)z);
        __threadfence();
        const unsigned done = atomicAdd(&g_done, 1u);
        if (done == (unsigned)gridDim.x - 1u) {
            double total = *(volatile double*)&g_sum;
            out[0] = (float)((g_base + total) * invN);
            g_sum = 0.0;     // reset for next graph replay
            g_done = 0u;
            g_cls[0] = 0; g_cls[1] = 0; g_cls[2] = 0; g_cls[3] = 0;
        }
    }
}

extern "C" void kernel_launch(void* const* d_in, const int* in_sizes, int n_in,
                              void* d_out, int out_size) {
    const float* x = (const float*)d_in[0];
    const int* traw = (const int*)d_in[1];
    float* out = (float*)d_out;

    const int n = in_sizes[1];          // 8192
    const double invN = 1.0 / (double)n;

    cudaFuncSetAttribute(relu_kernel, cudaFuncAttributeMaxDynamicSharedMemorySize, SMEM_TOTAL);

    fused_prep_kernel<<<CS_BLOCKS, 256>>>(x, traw, n);
    relu_kernel<<<GRID_RELU, 256, SMEM_TOTAL>>>(out, invN);
}